// round 3
// baseline (speedup 1.0000x reference)
#include <cuda_runtime.h>
#include <cstdint>

#define NPTS    131072
#define H       256
#define M       32          // points per block tile
#define MP      36          // padded row stride (floats): 144B -> 16B aligned rows
#define NLEV    4
#define FEAT    8
#define TMASK   32767u
#define THREADS 256

#define SMEM_FLOATS (2*H*MP + NLEV*FEAT*M + 3*M)
#define SMEM_BYTES  (SMEM_FLOATS * 4)

// ---------- packed f32x2 helpers (sm_103a) ----------
__device__ __forceinline__ unsigned long long pack2(float a, float b) {
    unsigned long long r;
    asm("mov.b64 %0, {%1, %2};" : "=l"(r) : "f"(a), "f"(b));
    return r;
}
__device__ __forceinline__ void unpack2(unsigned long long v, float& a, float& b) {
    asm("mov.b64 {%0, %1}, %2;" : "=f"(a), "=f"(b) : "l"(v));
}
__device__ __forceinline__ unsigned long long ffma2(unsigned long long a,
                                                    unsigned long long b,
                                                    unsigned long long c) {
    unsigned long long d;
    asm("fma.rn.f32x2 %0, %1, %2, %3;" : "=l"(d) : "l"(a), "l"(b), "l"(c));
    return d;
}

// ---------- fast sin: 2-term Cody-Waite reduction + MUFU ----------
// 2pi = 6.2831854820251465 (fp32 hi) + (-1.7484556e-7) (lo)
__device__ __forceinline__ float fast_sin(float x) {
    float k = rintf(x * 0.15915494309189535f);
    float r = fmaf(k, -6.2831854820251465f, x);
    r = fmaf(k, 1.7484556e-7f, r);
    return __sinf(r);   // |r| <= pi: MUFU.SIN abs err ~5e-7
}

// ---------- 256x256 GEMV-batch over the 32-point tile ----------
// shx layout: shx[k*MP + m], acc[q] holds points (2q, 2q+1) packed as f32x2.
__device__ __forceinline__ void gemm_tile(const float* __restrict__ Wg, float bias,
                                          const float* shx,
                                          unsigned long long* acc, int h)
{
    unsigned long long b2 = pack2(bias, bias);
#pragma unroll
    for (int q = 0; q < 16; q++) acc[q] = b2;
#pragma unroll 4
    for (int k = 0; k < H; k++) {
        float w = __ldg(Wg + (k << 8) + h);           // coalesced, L1/L2 hit
        unsigned long long w2 = pack2(w, w);
        const ulonglong2* xr = (const ulonglong2*)(shx + k * MP);  // 16B aligned
#pragma unroll
        for (int q = 0; q < 8; q++) {
            ulonglong2 xv = xr[q];                    // LDS.128 broadcast
            acc[2*q    ] = ffma2(xv.x, w2, acc[2*q    ]);
            acc[2*q + 1] = ffma2(xv.y, w2, acc[2*q + 1]);
        }
    }
}

__global__ void __launch_bounds__(THREADS, 2)
ffb_kernel(const float* __restrict__ in_pos,
           const float* __restrict__ table,
           const float* __restrict__ ffn_A,
           const float* __restrict__ W0,
           const float* __restrict__ b0,
           const float* __restrict__ Ws,
           const float* __restrict__ bs,
           const float* __restrict__ Wh,
           const float* __restrict__ bh,
           float* __restrict__ out)
{
    extern __shared__ float smem[];
    float* bufA  = smem;                       // H*MP floats (activations, transposed)
    float* bufB  = bufA + H * MP;              // H*MP floats
    float* shg   = bufB + H * MP;              // [4 levels * 8 feats][M]
    float* shpos = shg + NLEV * FEAT * M;      // [M][3]

    const int t    = threadIdx.x;              // hidden unit h
    const int base = blockIdx.x * M;

    if (t < 3 * M) shpos[t] = in_pos[base * 3 + t];
    __syncthreads();

    // ---- hash-grid encode: 8 lanes per point, one corner each ----
    {
        const int m = t >> 3;
        const int c = t & 7;
        const unsigned ox = (c >> 2) & 1u, oy = (c >> 1) & 1u, oz = c & 1u;
        // pos01 = (p + BOUND) / (2*BOUND), bit-identical to reference fp32 path
        const float px = (shpos[3*m + 0] + 1.0f) * 0.5f;
        const float py = (shpos[3*m + 1] + 1.0f) * 0.5f;
        const float pz = (shpos[3*m + 2] + 1.0f) * 0.5f;
#pragma unroll
        for (int l = 0; l < NLEV; l++) {
            const float res = (float)(16 << l);
            float sx = px * res, sy = py * res, sz = pz * res;
            float fx = floorf(sx), fy = floorf(sy), fz = floorf(sz);
            float rx = sx - fx, ry = sy - fy, rz = sz - fz;
            unsigned ux = (unsigned)fx + ox;
            unsigned uy = (unsigned)fy + oy;
            unsigned uz = (unsigned)fz + oz;
            unsigned idx = (ux ^ (uy * 2654435761u) ^ (uz * 805459861u)) & TMASK;
            const float4* fp = (const float4*)(table + ((size_t)(l << 15) + idx) * 8);
            float4 f0 = __ldg(fp), f1 = __ldg(fp + 1);
            float w = (ox ? rx : 1.0f - rx) * (oy ? ry : 1.0f - ry) * (oz ? rz : 1.0f - rz);
            float v[8] = { f0.x*w, f0.y*w, f0.z*w, f0.w*w,
                           f1.x*w, f1.y*w, f1.z*w, f1.w*w };
#pragma unroll
            for (int s = 1; s < 8; s <<= 1) {
#pragma unroll
                for (int j = 0; j < 8; j++)
                    v[j] += __shfl_xor_sync(0xffffffffu, v[j], s);
            }
            if (c == 0) {
#pragma unroll
                for (int j = 0; j < 8; j++)
                    shg[(l * FEAT + j) * M + m] = v[j];
            }
        }
    }

    // ---- layer 0: x = sin(pos @ W0 + b0) -> bufA (transposed) ----
    {
        const float wx = W0[t], wy = W0[H + t], wz = W0[2*H + t], bb = b0[t];
#pragma unroll
        for (int m = 0; m < M; m++) {
            float a = fmaf(shpos[3*m + 0], wx,
                      fmaf(shpos[3*m + 1], wy,
                      fmaf(shpos[3*m + 2], wz, bb)));
            bufA[t * MP + m] = fast_sin(a);
        }
    }
    __syncthreads();

    unsigned long long acc[16];
    float outacc[M];
#pragma unroll
    for (int m = 0; m < M; m++) outacc[m] = 0.0f;

#pragma unroll
    for (int l = 0; l < NLEV; l++) {
        const float* xin  = (l & 1) ? bufB : bufA;
        float*       xout = (l & 1) ? bufA : bufB;

        // x @ Ws[l] + bs[l]
        gemm_tile(Ws + l * H * H, bs[l * H + t], xin, acc, t);

        // grid branch: sin(2pi * sigma_l * (g . A_col))
        float Ac[FEAT];
        const float sc = 6.2831853071795864f * (float)(1 << l);
#pragma unroll
        for (int f = 0; f < FEAT; f++)
            Ac[f] = __ldg(ffn_A + ((l * FEAT + f) << 8) + t) * sc;

#pragma unroll
        for (int q = 0; q < 16; q++) {
            float s0, s1;
            unpack2(acc[q], s0, s1);
            const int m0 = 2 * q, m1 = m0 + 1;
            float g0 = 0.0f, g1 = 0.0f;
#pragma unroll
            for (int f = 0; f < FEAT; f++) {
                const float* gp = shg + (l * FEAT + f) * M;
                g0 = fmaf(gp[m0], Ac[f], g0);
                g1 = fmaf(gp[m1], Ac[f], g1);
            }
            float2 xv;
            xv.x = fast_sin(s0) + fast_sin(g0);
            xv.y = fast_sin(s1) + fast_sin(g1);
            *(float2*)(xout + t * MP + m0) = xv;   // st.shared.v2
        }
        __syncthreads();   // xout complete before anyone reads it

        // out += sin(x @ Wh[l] + bh[l])
        gemm_tile(Wh + l * H * H, bh[l * H + t], xout, acc, t);
#pragma unroll
        for (int q = 0; q < 16; q++) {
            float s0, s1;
            unpack2(acc[q], s0, s1);
            outacc[2*q    ] += fast_sin(s0);
            outacc[2*q + 1] += fast_sin(s1);
        }
    }

#pragma unroll
    for (int m = 0; m < M; m++)
        out[(size_t)(base + m) * H + t] = outacc[m];
}

extern "C" void kernel_launch(void* const* d_in, const int* in_sizes, int n_in,
                              void* d_out, int out_size)
{
    const float* in_pos = (const float*)d_in[0];
    const float* table  = (const float*)d_in[1];
    const float* ffn_A  = (const float*)d_in[2];
    const float* W0     = (const float*)d_in[3];
    const float* b0     = (const float*)d_in[4];
    const float* Ws     = (const float*)d_in[5];
    const float* bs     = (const float*)d_in[6];
    const float* Wh     = (const float*)d_in[7];
    const float* bh     = (const float*)d_in[8];
    float* out = (float*)d_out;

    // opt-in to >48KB dynamic smem (idempotent, not a stream op: capture-safe)
    cudaFuncSetAttribute(ffb_kernel, cudaFuncAttributeMaxDynamicSharedMemorySize, SMEM_BYTES);

    ffb_kernel<<<NPTS / M, THREADS, SMEM_BYTES>>>(in_pos, table, ffn_A, W0, b0,
                                                  Ws, bs, Wh, bh, out);
}